// round 1
// baseline (speedup 1.0000x reference)
#include <cuda_runtime.h>
#include <cstdio>

#define N_NODES 50000
#define MAX_E   800000
#define D_IN    128
#define D_HID   256
#define D_OUT   128

// ---------------- scratch (static device globals; no allocation) ----------------
__device__ float g_neigh1[(size_t)N_NODES * D_IN];    // mean of x over in-edges
__device__ float g_h1[(size_t)N_NODES * D_HID];       // relu(layer1)
__device__ float g_neigh2[(size_t)N_NODES * D_HID];   // mean of h1 over in-edges
__device__ float g_h2[(size_t)N_NODES * D_OUT];       // layer2 out
__device__ float g_sA[N_NODES];
__device__ float g_sB[N_NODES];
__device__ int   g_cnt[N_NODES];
__device__ int   g_rowptr[N_NODES + 1];
__device__ int   g_cursor[N_NODES];
__device__ int   g_csr_src[MAX_E];

// ---------------- CSR build ----------------
__global__ void k_zero_cnt() {
    int i = blockIdx.x * blockDim.x + threadIdx.x;
    if (i < N_NODES) g_cnt[i] = 0;
}

__global__ void k_hist(const int* __restrict__ dst, int E) {
    int e = blockIdx.x * blockDim.x + threadIdx.x;
    if (e < E) atomicAdd(&g_cnt[dst[e]], 1);
}

// single-block exclusive scan of g_cnt -> g_rowptr / g_cursor
__global__ void k_scan() {
    const int T = 1024;
    const int C = (N_NODES + T - 1) / T;   // 49
    __shared__ int partial[T];
    int t = threadIdx.x;
    int base = t * C;
    int s = 0;
    for (int i = 0; i < C; i++) {
        int idx = base + i;
        if (idx < N_NODES) s += g_cnt[idx];
    }
    partial[t] = s;
    __syncthreads();
    // Hillis-Steele inclusive scan
    for (int off = 1; off < T; off <<= 1) {
        int v = (t >= off) ? partial[t - off] : 0;
        __syncthreads();
        partial[t] += v;
        __syncthreads();
    }
    int run = partial[t] - s;   // exclusive prefix for this chunk
    for (int i = 0; i < C; i++) {
        int idx = base + i;
        if (idx < N_NODES) {
            g_rowptr[idx] = run;
            g_cursor[idx] = run;
            run += g_cnt[idx];
        }
    }
    if (t == 0) g_rowptr[N_NODES] = partial[T - 1];
}

__global__ void k_fill(const int* __restrict__ src, const int* __restrict__ dst, int E) {
    int e = blockIdx.x * blockDim.x + threadIdx.x;
    if (e < E) {
        int d = dst[e];
        int pos = atomicAdd(&g_cursor[d], 1);
        g_csr_src[pos] = src[e];
    }
}

// ---------------- gather-mean aggregation (warp per node, no atomics) ----------------
template <int D>
__global__ void k_agg(const float* __restrict__ feat, float* __restrict__ out) {
    int warps_per_blk = blockDim.x >> 5;
    int n = blockIdx.x * warps_per_blk + (threadIdx.x >> 5);
    if (n >= N_NODES) return;
    int lane = threadIdx.x & 31;
    int beg = g_rowptr[n], end = g_rowptr[n + 1];

    float4 acc0 = {0.f, 0.f, 0.f, 0.f};
    float4 acc1 = {0.f, 0.f, 0.f, 0.f};
    for (int j = beg; j < end; j++) {
        int s = g_csr_src[j];
        const float4* row = (const float4*)(feat + (size_t)s * D);
        float4 v = __ldg(&row[lane]);
        acc0.x += v.x; acc0.y += v.y; acc0.z += v.z; acc0.w += v.w;
        if (D == 256) {
            float4 v2 = __ldg(&row[lane + 32]);
            acc1.x += v2.x; acc1.y += v2.y; acc1.z += v2.z; acc1.w += v2.w;
        }
    }
    int deg = end - beg;
    float inv = (deg > 0) ? 1.f / (float)deg : 0.f;
    float4* orow = (float4*)(out + (size_t)n * D);
    float4 o0 = {acc0.x * inv, acc0.y * inv, acc0.z * inv, acc0.w * inv};
    orow[lane] = o0;
    if (D == 256) {
        float4 o1 = {acc1.x * inv, acc1.y * inv, acc1.z * inv, acc1.w * inv};
        orow[lane + 32] = o1;
    }
}

// ---------------- fused dual GEMM: C = act(A1@B1 + A2@B2 + bias) ----------------
// A1,A2: MxK row-major; B1,B2: KxN row-major; C: MxN. N%64==0, K%16==0.
template <bool RELU>
__global__ void __launch_bounds__(256) k_gemm(
    const float* __restrict__ A1, const float* __restrict__ A2,
    const float* __restrict__ B1, const float* __restrict__ B2,
    const float* __restrict__ bias, float* __restrict__ C,
    int M, int N, int K)
{
    const int BM = 64, BN = 64, BK = 16;
    __shared__ float As1[BK][BM], As2[BK][BM];
    __shared__ float Bs1[BK][BN], Bs2[BK][BN];

    int tid = threadIdx.x;
    int bm = blockIdx.y * BM, bn = blockIdx.x * BN;
    int tx = tid & 15, ty = tid >> 4;
    int arow = tid >> 2, ak = (tid & 3) * 4;
    int brow = tid >> 4, bc = (tid & 15) * 4;

    float acc[4][4];
#pragma unroll
    for (int i = 0; i < 4; i++)
#pragma unroll
        for (int j = 0; j < 4; j++) acc[i][j] = 0.f;

    for (int k0 = 0; k0 < K; k0 += BK) {
        float4 a1 = {0.f, 0.f, 0.f, 0.f}, a2 = {0.f, 0.f, 0.f, 0.f};
        int gr = bm + arow;
        if (gr < M) {
            a1 = *(const float4*)(A1 + (size_t)gr * K + k0 + ak);
            a2 = *(const float4*)(A2 + (size_t)gr * K + k0 + ak);
        }
        As1[ak + 0][arow] = a1.x; As1[ak + 1][arow] = a1.y;
        As1[ak + 2][arow] = a1.z; As1[ak + 3][arow] = a1.w;
        As2[ak + 0][arow] = a2.x; As2[ak + 1][arow] = a2.y;
        As2[ak + 2][arow] = a2.z; As2[ak + 3][arow] = a2.w;
        *(float4*)&Bs1[brow][bc] = *(const float4*)(B1 + (size_t)(k0 + brow) * N + bn + bc);
        *(float4*)&Bs2[brow][bc] = *(const float4*)(B2 + (size_t)(k0 + brow) * N + bn + bc);
        __syncthreads();

#pragma unroll
        for (int k = 0; k < BK; k++) {
            float4 va1 = *(float4*)&As1[k][ty * 4];
            float4 va2 = *(float4*)&As2[k][ty * 4];
            float4 vb1 = *(float4*)&Bs1[k][tx * 4];
            float4 vb2 = *(float4*)&Bs2[k][tx * 4];
            float a1r[4] = {va1.x, va1.y, va1.z, va1.w};
            float a2r[4] = {va2.x, va2.y, va2.z, va2.w};
            float b1r[4] = {vb1.x, vb1.y, vb1.z, vb1.w};
            float b2r[4] = {vb2.x, vb2.y, vb2.z, vb2.w};
#pragma unroll
            for (int i = 0; i < 4; i++)
#pragma unroll
                for (int j = 0; j < 4; j++)
                    acc[i][j] += a1r[i] * b1r[j] + a2r[i] * b2r[j];
        }
        __syncthreads();
    }

    float4 bv = *(const float4*)(bias + bn + tx * 4);
#pragma unroll
    for (int i = 0; i < 4; i++) {
        int r = bm + ty * 4 + i;
        if (r >= M) continue;
        float4 c;
        c.x = acc[i][0] + bv.x; c.y = acc[i][1] + bv.y;
        c.z = acc[i][2] + bv.z; c.w = acc[i][3] + bv.w;
        if (RELU) {
            c.x = fmaxf(c.x, 0.f); c.y = fmaxf(c.y, 0.f);
            c.z = fmaxf(c.z, 0.f); c.w = fmaxf(c.w, 0.f);
        }
        *(float4*)(C + (size_t)r * N + bn + tx * 4) = c;
    }
}

// ---------------- per-node score halves: sA = h2 . Wp[:128], sB = h2 . Wp[128:] ----------------
__global__ void k_node_scores(const float* __restrict__ h2, const float* __restrict__ Wp) {
    int warps_per_blk = blockDim.x >> 5;
    int n = blockIdx.x * warps_per_blk + (threadIdx.x >> 5);
    if (n >= N_NODES) return;
    int lane = threadIdx.x & 31;
    float4 v  = __ldg(&((const float4*)(h2 + (size_t)n * D_OUT))[lane]);
    float4 wa = __ldg(&((const float4*)Wp)[lane]);
    float4 wb = __ldg(&((const float4*)Wp)[lane + 32]);
    float a = v.x * wa.x + v.y * wa.y + v.z * wa.z + v.w * wa.w;
    float b = v.x * wb.x + v.y * wb.y + v.z * wb.z + v.w * wb.w;
#pragma unroll
    for (int off = 16; off; off >>= 1) {
        a += __shfl_down_sync(0xFFFFFFFFu, a, off);
        b += __shfl_down_sync(0xFFFFFFFFu, b, off);
    }
    if (lane == 0) { g_sA[n] = a; g_sB[n] = b; }
}

__global__ void k_edge_scores(const int* __restrict__ psrc, const int* __restrict__ pdst,
                              const int* __restrict__ nsrc, const int* __restrict__ ndst,
                              const float* __restrict__ bp, float* __restrict__ out,
                              int EP, int EN) {
    int i = blockIdx.x * blockDim.x + threadIdx.x;
    float b = bp[0];
    if (i < EP) {
        out[i] = g_sA[psrc[i]] + g_sB[pdst[i]] + b;
    } else if (i < EP + EN) {
        int j = i - EP;
        out[i] = g_sA[nsrc[j]] + g_sB[ndst[j]] + b;
    }
}

// ---------------- launch ----------------
extern "C" void kernel_launch(void* const* d_in, const int* in_sizes, int n_in,
                              void* d_out, int out_size) {
    const float* x    = (const float*)d_in[0];
    const int* msrc   = (const int*)d_in[1];
    const int* mdst   = (const int*)d_in[2];
    const int* psrc   = (const int*)d_in[3];
    const int* pdst   = (const int*)d_in[4];
    const int* nsrc   = (const int*)d_in[5];
    const int* ndst   = (const int*)d_in[6];
    const float* W1s  = (const float*)d_in[7];
    const float* W1n  = (const float*)d_in[8];
    const float* b1   = (const float*)d_in[9];
    const float* W2s  = (const float*)d_in[10];
    const float* W2n  = (const float*)d_in[11];
    const float* b2   = (const float*)d_in[12];
    const float* Wp   = (const float*)d_in[13];
    const float* bp   = (const float*)d_in[14];
    float* out = (float*)d_out;

    int E  = in_sizes[1];
    int EP = in_sizes[3];
    int EN = in_sizes[5];

    float *p_neigh1, *p_h1, *p_neigh2, *p_h2;
    cudaGetSymbolAddress((void**)&p_neigh1, g_neigh1);
    cudaGetSymbolAddress((void**)&p_h1,     g_h1);
    cudaGetSymbolAddress((void**)&p_neigh2, g_neigh2);
    cudaGetSymbolAddress((void**)&p_h2,     g_h2);

    // CSR build (once; same edge set for both layers)
    k_zero_cnt<<<(N_NODES + 255) / 256, 256>>>();
    k_hist<<<(E + 255) / 256, 256>>>(mdst, E);
    k_scan<<<1, 1024>>>();
    k_fill<<<(E + 255) / 256, 256>>>(msrc, mdst, E);

    // layer 1
    k_agg<D_IN><<<(N_NODES + 7) / 8, 256>>>(x, p_neigh1);
    {
        dim3 grid(D_HID / 64, (N_NODES + 63) / 64);
        k_gemm<true><<<grid, 256>>>(x, p_neigh1, W1s, W1n, b1, p_h1,
                                    N_NODES, D_HID, D_IN);
    }
    // layer 2
    k_agg<D_HID><<<(N_NODES + 7) / 8, 256>>>(p_h1, p_neigh2);
    {
        dim3 grid(D_OUT / 64, (N_NODES + 63) / 64);
        k_gemm<false><<<grid, 256>>>(p_h1, p_neigh2, W2s, W2n, b2, p_h2,
                                     N_NODES, D_OUT, D_HID);
    }

    // edge scoring
    k_node_scores<<<(N_NODES + 7) / 8, 256>>>(p_h2, Wp);
    k_edge_scores<<<(EP + EN + 255) / 256, 256>>>(psrc, pdst, nsrc, ndst, bp, out, EP, EN);
}

// round 3
// speedup vs baseline: 1.0825x; 1.0825x over previous
#include <cuda_runtime.h>
#include <cstdint>

#define N_NODES 50000
#define MAX_E   800000
#define D_IN    128
#define D_HID   256
#define D_OUT   128

// ---------------- scratch (static device globals; no allocation) ----------------
__device__ float g_neigh1[(size_t)N_NODES * D_IN];   // mean of x over in-edges
__device__ float g_h1[(size_t)N_NODES * D_HID];      // relu(layer1)
__device__ float g_s2[(size_t)N_NODES * D_OUT];      // h1 @ W2_self + b2
__device__ float g_t2[(size_t)N_NODES * D_OUT];      // h1 @ W2_neigh (pre-aggregation projection)
__device__ float g_sA[N_NODES];
__device__ float g_sB[N_NODES];
__device__ int   g_cnt[N_NODES];
__device__ int   g_rowptr[N_NODES + 1];
__device__ int   g_cursor[N_NODES];
__device__ int   g_csr_src[MAX_E];

// ---------------- packed f32x2 helpers ----------------
__device__ __forceinline__ void fma2(unsigned long long& d,
                                     unsigned long long a,
                                     unsigned long long b) {
    asm("fma.rn.f32x2 %0, %1, %2, %0;" : "+l"(d) : "l"(a), "l"(b));
}
__device__ __forceinline__ unsigned long long pack_dup(float v) {
    unsigned int u = __float_as_uint(v);
    return ((unsigned long long)u << 32) | (unsigned long long)u;
}
__device__ __forceinline__ float2 unpack2(unsigned long long p) {
    float2 f;
    f.x = __uint_as_float((unsigned int)p);
    f.y = __uint_as_float((unsigned int)(p >> 32));
    return f;
}

// ---------------- CSR build ----------------
__global__ void k_zero_cnt() {
    int i = blockIdx.x * blockDim.x + threadIdx.x;
    if (i < N_NODES) g_cnt[i] = 0;
}
__global__ void k_hist(const int* __restrict__ dst, int E) {
    int e = blockIdx.x * blockDim.x + threadIdx.x;
    if (e < E) atomicAdd(&g_cnt[dst[e]], 1);
}
__global__ void k_scan() {
    const int T = 1024;
    const int C = (N_NODES + T - 1) / T;
    __shared__ int partial[T];
    int t = threadIdx.x;
    int base = t * C;
    int s = 0;
    for (int i = 0; i < C; i++) {
        int idx = base + i;
        if (idx < N_NODES) s += g_cnt[idx];
    }
    partial[t] = s;
    __syncthreads();
    for (int off = 1; off < T; off <<= 1) {
        int v = (t >= off) ? partial[t - off] : 0;
        __syncthreads();
        partial[t] += v;
        __syncthreads();
    }
    int run = partial[t] - s;
    for (int i = 0; i < C; i++) {
        int idx = base + i;
        if (idx < N_NODES) {
            g_rowptr[idx] = run;
            g_cursor[idx] = run;
            run += g_cnt[idx];
        }
    }
    if (t == 0) g_rowptr[N_NODES] = partial[T - 1];
}
__global__ void k_fill(const int* __restrict__ src, const int* __restrict__ dst, int E) {
    int e = blockIdx.x * blockDim.x + threadIdx.x;
    if (e < E) {
        int d = dst[e];
        int pos = atomicAdd(&g_cursor[d], 1);
        g_csr_src[pos] = src[e];
    }
}

// ---------------- layer-1 aggregation: neigh1[n] = mean_{e: dst=n} x[src_e] ----------------
__global__ void k_agg128(const float* __restrict__ feat, float* __restrict__ out) {
    int warps_per_blk = blockDim.x >> 5;
    int n = blockIdx.x * warps_per_blk + (threadIdx.x >> 5);
    if (n >= N_NODES) return;
    int lane = threadIdx.x & 31;
    int beg = g_rowptr[n], end = g_rowptr[n + 1];

    float4 acc = {0.f, 0.f, 0.f, 0.f};
    for (int j = beg; j < end; j++) {
        int s = g_csr_src[j];
        float4 v = __ldg(&((const float4*)(feat + (size_t)s * 128))[lane]);
        acc.x += v.x; acc.y += v.y; acc.z += v.z; acc.w += v.w;
    }
    int deg = end - beg;
    float inv = (deg > 0) ? 1.f / (float)deg : 0.f;
    float4 o = {acc.x * inv, acc.y * inv, acc.z * inv, acc.w * inv};
    ((float4*)(out + (size_t)n * 128))[lane] = o;
}

// ================= packed-f32x2 SIMT GEMMs =================
// Tile 64(M) x 64(N) x 16(K), 256 threads, 4x4 outputs/thread (as 4x2 packed pairs).
#define BM 64
#define BN 64
#define BK 16
#define APAD 66   // ulonglong row stride: 528B = multiple of 16, bank-conflict-free columns

// -------- dual-A GEMM: C = act(A1@B1 + A2@B2 + bias), B's are (K,N) row-major --------
template <bool RELU>
__global__ void __launch_bounds__(256) k_gemm_dual(
    const float* __restrict__ A1, const float* __restrict__ A2,
    const float* __restrict__ B1, const float* __restrict__ B2,
    const float* __restrict__ bias, float* __restrict__ C,
    int M, int N, int K)
{
    __shared__ unsigned long long As1[BK][APAD];
    __shared__ unsigned long long As2[BK][APAD];
    __shared__ float Bs1[BK][BN];
    __shared__ float Bs2[BK][BN];

    int tid = threadIdx.x;
    int bm = blockIdx.y * BM, bn = blockIdx.x * BN;
    int tx = tid & 15, ty = tid >> 4;
    int arow = tid >> 2, ak = (tid & 3) * 4;
    int brow = tid >> 4, bc = (tid & 15) * 4;

    unsigned long long acc[4][2];
#pragma unroll
    for (int i = 0; i < 4; i++) { acc[i][0] = 0ull; acc[i][1] = 0ull; }

    for (int k0 = 0; k0 < K; k0 += BK) {
        float4 a1 = {0.f, 0.f, 0.f, 0.f}, a2 = {0.f, 0.f, 0.f, 0.f};
        int gr = bm + arow;
        if (gr < M) {
            a1 = *(const float4*)(A1 + (size_t)gr * K + k0 + ak);
            a2 = *(const float4*)(A2 + (size_t)gr * K + k0 + ak);
        }
        As1[ak + 0][arow] = pack_dup(a1.x);
        As1[ak + 1][arow] = pack_dup(a1.y);
        As1[ak + 2][arow] = pack_dup(a1.z);
        As1[ak + 3][arow] = pack_dup(a1.w);
        As2[ak + 0][arow] = pack_dup(a2.x);
        As2[ak + 1][arow] = pack_dup(a2.y);
        As2[ak + 2][arow] = pack_dup(a2.z);
        As2[ak + 3][arow] = pack_dup(a2.w);
        *(float4*)&Bs1[brow][bc] = *(const float4*)(B1 + (size_t)(k0 + brow) * N + bn + bc);
        *(float4*)&Bs2[brow][bc] = *(const float4*)(B2 + (size_t)(k0 + brow) * N + bn + bc);
        __syncthreads();

#pragma unroll
        for (int k = 0; k < BK; k++) {
            ulonglong2 a1lo = *(ulonglong2*)&As1[k][ty * 4];
            ulonglong2 a1hi = *(ulonglong2*)&As1[k][ty * 4 + 2];
            ulonglong2 a2lo = *(ulonglong2*)&As2[k][ty * 4];
            ulonglong2 a2hi = *(ulonglong2*)&As2[k][ty * 4 + 2];
            ulonglong2 b1p = *(ulonglong2*)&Bs1[k][tx * 4];
            ulonglong2 b2p = *(ulonglong2*)&Bs2[k][tx * 4];
            fma2(acc[0][0], a1lo.x, b1p.x); fma2(acc[0][1], a1lo.x, b1p.y);
            fma2(acc[1][0], a1lo.y, b1p.x); fma2(acc[1][1], a1lo.y, b1p.y);
            fma2(acc[2][0], a1hi.x, b1p.x); fma2(acc[2][1], a1hi.x, b1p.y);
            fma2(acc[3][0], a1hi.y, b1p.x); fma2(acc[3][1], a1hi.y, b1p.y);
            fma2(acc[0][0], a2lo.x, b2p.x); fma2(acc[0][1], a2lo.x, b2p.y);
            fma2(acc[1][0], a2lo.y, b2p.x); fma2(acc[1][1], a2lo.y, b2p.y);
            fma2(acc[2][0], a2hi.x, b2p.x); fma2(acc[2][1], a2hi.x, b2p.y);
            fma2(acc[3][0], a2hi.y, b2p.x); fma2(acc[3][1], a2hi.y, b2p.y);
        }
        __syncthreads();
    }

    float4 bv = *(const float4*)(bias + bn + tx * 4);
#pragma unroll
    for (int i = 0; i < 4; i++) {
        int r = bm + ty * 4 + i;
        if (r >= M) continue;
        float2 c0 = unpack2(acc[i][0]);
        float2 c1 = unpack2(acc[i][1]);
        float4 c;
        c.x = c0.x + bv.x; c.y = c0.y + bv.y;
        c.z = c1.x + bv.z; c.w = c1.y + bv.w;
        if (RELU) {
            c.x = fmaxf(c.x, 0.f); c.y = fmaxf(c.y, 0.f);
            c.z = fmaxf(c.z, 0.f); c.w = fmaxf(c.w, 0.f);
        }
        *(float4*)(C + (size_t)r * N + bn + tx * 4) = c;
    }
}

// -------- single-A / dual-B GEMM: S = A@Bs + bias, T = A@Bt --------
__global__ void __launch_bounds__(256) k_gemm_pair(
    const float* __restrict__ A,
    const float* __restrict__ Bsw, const float* __restrict__ Btw,
    const float* __restrict__ bias,
    float* __restrict__ S, float* __restrict__ T,
    int M, int N, int K)
{
    __shared__ unsigned long long As[BK][APAD];
    __shared__ float Bs1[BK][BN];
    __shared__ float Bs2[BK][BN];

    int tid = threadIdx.x;
    int bm = blockIdx.y * BM, bn = blockIdx.x * BN;
    int tx = tid & 15, ty = tid >> 4;
    int arow = tid >> 2, ak = (tid & 3) * 4;
    int brow = tid >> 4, bc = (tid & 15) * 4;

    unsigned long long accS[4][2], accT[4][2];
#pragma unroll
    for (int i = 0; i < 4; i++) {
        accS[i][0] = 0ull; accS[i][1] = 0ull;
        accT[i][0] = 0ull; accT[i][1] = 0ull;
    }

    for (int k0 = 0; k0 < K; k0 += BK) {
        float4 a = {0.f, 0.f, 0.f, 0.f};
        int gr = bm + arow;
        if (gr < M) a = *(const float4*)(A + (size_t)gr * K + k0 + ak);
        As[ak + 0][arow] = pack_dup(a.x);
        As[ak + 1][arow] = pack_dup(a.y);
        As[ak + 2][arow] = pack_dup(a.z);
        As[ak + 3][arow] = pack_dup(a.w);
        *(float4*)&Bs1[brow][bc] = *(const float4*)(Bsw + (size_t)(k0 + brow) * N + bn + bc);
        *(float4*)&Bs2[brow][bc] = *(const float4*)(Btw + (size_t)(k0 + brow) * N + bn + bc);
        __syncthreads();

#pragma unroll
        for (int k = 0; k < BK; k++) {
            ulonglong2 alo = *(ulonglong2*)&As[k][ty * 4];
            ulonglong2 ahi = *(ulonglong2*)&As[k][ty * 4 + 2];
            ulonglong2 b1p = *(ulonglong2*)&Bs1[k][tx * 4];
            ulonglong2 b2p = *(ulonglong2*)&Bs2[k][tx * 4];
            fma2(accS[0][0], alo.x, b1p.x); fma2(accS[0][1], alo.x, b1p.y);
            fma2(accS[1][0], alo.y, b1p.x); fma2(accS[1][1], alo.y, b1p.y);
            fma2(accS[2][0], ahi.x, b1p.x); fma2(accS[2][1], ahi.x, b1p.y);
            fma2(accS[3][0], ahi.y, b1p.x); fma2(accS[3][1], ahi.y, b1p.y);
            fma2(accT[0][0], alo.x, b2p.x); fma2(accT[0][1], alo.x, b2p.y);
            fma2(accT[1][0], alo.y, b2p.x); fma2(accT[1][1], alo.y, b2p.y);
            fma2(accT[2][0], ahi.x, b2p.x); fma2(accT[2][1], ahi.x, b2p.y);
            fma2(accT[3][0], ahi.y, b2p.x); fma2(accT[3][1], ahi.y, b2p.y);
        }
        __syncthreads();
    }

    float4 bv = *(const float4*)(bias + bn + tx * 4);
#pragma unroll
    for (int i = 0; i < 4; i++) {
        int r = bm + ty * 4 + i;
        if (r >= M) continue;
        float2 s0 = unpack2(accS[i][0]);
        float2 s1 = unpack2(accS[i][1]);
        float4 cs = {s0.x + bv.x, s0.y + bv.y, s1.x + bv.z, s1.y + bv.w};
        *(float4*)(S + (size_t)r * N + bn + tx * 4) = cs;
        float2 t0 = unpack2(accT[i][0]);
        float2 t1 = unpack2(accT[i][1]);
        float4 ct = {t0.x, t0.y, t1.x, t1.y};
        *(float4*)(T + (size_t)r * N + bn + tx * 4) = ct;
    }
}

// ---------------- fused layer-2 aggregation + node scores ----------------
// h2[n] = s2[n] + mean_{e: dst=n} t2[src_e]   (bias already in s2)
// sA[n] = h2[n].Wp[:128], sB[n] = h2[n].Wp[128:]
__global__ void k_agg2_scores(const float* __restrict__ Wp) {
    int warps_per_blk = blockDim.x >> 5;
    int n = blockIdx.x * warps_per_blk + (threadIdx.x >> 5);
    if (n >= N_NODES) return;
    int lane = threadIdx.x & 31;
    int beg = g_rowptr[n], end = g_rowptr[n + 1];

    float4 acc = {0.f, 0.f, 0.f, 0.f};
    for (int j = beg; j < end; j++) {
        int s = g_csr_src[j];
        float4 v = __ldg(&((const float4*)(g_t2 + (size_t)s * 128))[lane]);
        acc.x += v.x; acc.y += v.y; acc.z += v.z; acc.w += v.w;
    }
    int deg = end - beg;
    float inv = (deg > 0) ? 1.f / (float)deg : 0.f;
    float4 sv = ((const float4*)(g_s2 + (size_t)n * 128))[lane];
    float4 h;
    h.x = sv.x + acc.x * inv;
    h.y = sv.y + acc.y * inv;
    h.z = sv.z + acc.z * inv;
    h.w = sv.w + acc.w * inv;

    float4 wa = __ldg(&((const float4*)Wp)[lane]);
    float4 wb = __ldg(&((const float4*)Wp)[lane + 32]);
    float a = h.x * wa.x + h.y * wa.y + h.z * wa.z + h.w * wa.w;
    float b = h.x * wb.x + h.y * wb.y + h.z * wb.z + h.w * wb.w;
#pragma unroll
    for (int off = 16; off; off >>= 1) {
        a += __shfl_down_sync(0xFFFFFFFFu, a, off);
        b += __shfl_down_sync(0xFFFFFFFFu, b, off);
    }
    if (lane == 0) { g_sA[n] = a; g_sB[n] = b; }
}

__global__ void k_edge_scores(const int* __restrict__ psrc, const int* __restrict__ pdst,
                              const int* __restrict__ nsrc, const int* __restrict__ ndst,
                              const float* __restrict__ bp, float* __restrict__ out,
                              int EP, int EN) {
    int i = blockIdx.x * blockDim.x + threadIdx.x;
    float b = bp[0];
    if (i < EP) {
        out[i] = g_sA[psrc[i]] + g_sB[pdst[i]] + b;
    } else if (i < EP + EN) {
        int j = i - EP;
        out[i] = g_sA[nsrc[j]] + g_sB[ndst[j]] + b;
    }
}

// ---------------- launch ----------------
extern "C" void kernel_launch(void* const* d_in, const int* in_sizes, int n_in,
                              void* d_out, int out_size) {
    const float* x    = (const float*)d_in[0];
    const int* msrc   = (const int*)d_in[1];
    const int* mdst   = (const int*)d_in[2];
    const int* psrc   = (const int*)d_in[3];
    const int* pdst   = (const int*)d_in[4];
    const int* nsrc   = (const int*)d_in[5];
    const int* ndst   = (const int*)d_in[6];
    const float* W1s  = (const float*)d_in[7];
    const float* W1n  = (const float*)d_in[8];
    const float* b1   = (const float*)d_in[9];
    const float* W2s  = (const float*)d_in[10];
    const float* W2n  = (const float*)d_in[11];
    const float* b2   = (const float*)d_in[12];
    const float* Wp   = (const float*)d_in[13];
    const float* bp   = (const float*)d_in[14];
    float* out = (float*)d_out;

    int E  = in_sizes[1];
    int EP = in_sizes[3];
    int EN = in_sizes[5];

    float *p_neigh1, *p_h1, *p_s2, *p_t2;
    cudaGetSymbolAddress((void**)&p_neigh1, g_neigh1);
    cudaGetSymbolAddress((void**)&p_h1,     g_h1);
    cudaGetSymbolAddress((void**)&p_s2,     g_s2);
    cudaGetSymbolAddress((void**)&p_t2,     g_t2);

    // CSR build (by dst; shared by both layers)
    k_zero_cnt<<<(N_NODES + 255) / 256, 256>>>();
    k_hist<<<(E + 255) / 256, 256>>>(mdst, E);
    k_scan<<<1, 1024>>>();
    k_fill<<<(E + 255) / 256, 256>>>(msrc, mdst, E);

    // layer 1: aggregate x (128-d), then dual GEMM -> h1 (relu)
    k_agg128<<<(N_NODES + 7) / 8, 256>>>(x, p_neigh1);
    {
        dim3 grid(D_HID / BN, (N_NODES + BM - 1) / BM);
        k_gemm_dual<true><<<grid, 256>>>(x, p_neigh1, W1s, W1n, b1, p_h1,
                                         N_NODES, D_HID, D_IN);
    }

    // layer 2: project first (s2 = h1@W2s + b2, t2 = h1@W2n), then aggregate in 128-d
    {
        dim3 grid(D_OUT / BN, (N_NODES + BM - 1) / BM);
        k_gemm_pair<<<grid, 256>>>(p_h1, W2s, W2n, b2, p_s2, p_t2,
                                   N_NODES, D_OUT, D_HID);
    }
    k_agg2_scores<<<(N_NODES + 7) / 8, 256>>>(Wp);

    // edge scoring
    k_edge_scores<<<(EP + EN + 255) / 256, 256>>>(psrc, pdst, nsrc, ndst, bp, out, EP, EN);
}

// round 5
// speedup vs baseline: 1.9123x; 1.7665x over previous
#include <cuda_runtime.h>
#include <cuda_bf16.h>
#include <cstdint>

#define N_NODES 50000
#define MAX_E   800000
#define D_IN    128
#define D_HID   256
#define D_OUT   128

// ---------------- scratch (static device globals; no allocation) ----------------
__device__ float g_neigh1[(size_t)N_NODES * D_IN];
__device__ float g_h1[(size_t)N_NODES * D_HID];
__device__ float g_s2[(size_t)N_NODES * D_OUT];
__device__ float g_t2[(size_t)N_NODES * D_OUT];
__device__ float g_sA[N_NODES];
__device__ float g_sB[N_NODES];
__device__ int   g_cnt[N_NODES];
__device__ int   g_rowptr[N_NODES + 1];
__device__ int   g_cursor[N_NODES];
__device__ int   g_csr_src[MAX_E];

// pre-split bf16 weights, same (K,N) layout as the fp32 originals
__device__ __nv_bfloat16 g_w1s_h[D_IN * D_HID], g_w1s_l[D_IN * D_HID];
__device__ __nv_bfloat16 g_w1n_h[D_IN * D_HID], g_w1n_l[D_IN * D_HID];
__device__ __nv_bfloat16 g_w2s_h[D_HID * D_OUT], g_w2s_l[D_HID * D_OUT];
__device__ __nv_bfloat16 g_w2n_h[D_HID * D_OUT], g_w2n_l[D_HID * D_OUT];

// ---------------- helpers ----------------
__device__ __forceinline__ uint32_t smem_u32(const void* p) {
    uint32_t a;
    asm("{ .reg .u64 t; cvta.to.shared.u64 t, %1; cvt.u32.u64 %0, t; }" : "=r"(a) : "l"(p));
    return a;
}
__device__ __forceinline__ uint32_t bpack(__nv_bfloat16 a, __nv_bfloat16 b) {
    return (uint32_t)__bfloat16_as_ushort(a) | ((uint32_t)__bfloat16_as_ushort(b) << 16);
}
// split float4 -> bf16 hi pair-words + lo pair-words
__device__ __forceinline__ void split4(float4 v, uint32_t* h, uint32_t* l) {
    __nv_bfloat16 hx = __float2bfloat16_rn(v.x);
    __nv_bfloat16 hy = __float2bfloat16_rn(v.y);
    __nv_bfloat16 hz = __float2bfloat16_rn(v.z);
    __nv_bfloat16 hw = __float2bfloat16_rn(v.w);
    h[0] = bpack(hx, hy);
    h[1] = bpack(hz, hw);
    __nv_bfloat16 lx = __float2bfloat16_rn(v.x - __bfloat162float(hx));
    __nv_bfloat16 ly = __float2bfloat16_rn(v.y - __bfloat162float(hy));
    __nv_bfloat16 lz = __float2bfloat16_rn(v.z - __bfloat162float(hz));
    __nv_bfloat16 lw = __float2bfloat16_rn(v.w - __bfloat162float(hw));
    l[0] = bpack(lx, ly);
    l[1] = bpack(lz, lw);
}

#define LDSM_X4(r0, r1, r2, r3, addr) \
    asm volatile("ldmatrix.sync.aligned.m8n8.x4.shared.b16 {%0,%1,%2,%3}, [%4];" \
                 : "=r"(r0), "=r"(r1), "=r"(r2), "=r"(r3) : "r"(addr))
#define LDSM_X4T(r0, r1, r2, r3, addr) \
    asm volatile("ldmatrix.sync.aligned.m8n8.x4.trans.shared.b16 {%0,%1,%2,%3}, [%4];" \
                 : "=r"(r0), "=r"(r1), "=r"(r2), "=r"(r3) : "r"(addr))
#define MMA_BF16(c, a, b) \
    asm volatile("mma.sync.aligned.m16n8k16.row.col.f32.bf16.bf16.f32 " \
                 "{%0,%1,%2,%3}, {%4,%5,%6,%7}, {%8,%9}, {%0,%1,%2,%3};" \
                 : "+f"((c)[0]), "+f"((c)[1]), "+f"((c)[2]), "+f"((c)[3]) \
                 : "r"((a)[0]), "r"((a)[1]), "r"((a)[2]), "r"((a)[3]), \
                   "r"((b)[0]), "r"((b)[1]))

// ---------------- CSR build ----------------
__global__ void k_zero_cnt() {
    int i = blockIdx.x * blockDim.x + threadIdx.x;
    if (i < N_NODES) g_cnt[i] = 0;
}
__global__ void k_hist(const int* __restrict__ dst, int E) {
    int e = blockIdx.x * blockDim.x + threadIdx.x;
    if (e < E) atomicAdd(&g_cnt[dst[e]], 1);
}
__global__ void k_scan() {
    const int T = 1024;
    const int C = (N_NODES + T - 1) / T;
    __shared__ int partial[T];
    int t = threadIdx.x;
    int base = t * C;
    int s = 0;
    for (int i = 0; i < C; i++) {
        int idx = base + i;
        if (idx < N_NODES) s += g_cnt[idx];
    }
    partial[t] = s;
    __syncthreads();
    for (int off = 1; off < T; off <<= 1) {
        int v = (t >= off) ? partial[t - off] : 0;
        __syncthreads();
        partial[t] += v;
        __syncthreads();
    }
    int run = partial[t] - s;
    for (int i = 0; i < C; i++) {
        int idx = base + i;
        if (idx < N_NODES) {
            g_rowptr[idx] = run;
            g_cursor[idx] = run;
            run += g_cnt[idx];
        }
    }
    if (t == 0) g_rowptr[N_NODES] = partial[T - 1];
}
__global__ void k_fill(const int* __restrict__ src, const int* __restrict__ dst, int E) {
    int e = blockIdx.x * blockDim.x + threadIdx.x;
    if (e < E) {
        int d = dst[e];
        int pos = atomicAdd(&g_cursor[d], 1);
        g_csr_src[pos] = src[e];
    }
}

// ---------------- layer-1 aggregation ----------------
__global__ void k_agg128(const float* __restrict__ feat, float* __restrict__ out) {
    int warps_per_blk = blockDim.x >> 5;
    int n = blockIdx.x * warps_per_blk + (threadIdx.x >> 5);
    if (n >= N_NODES) return;
    int lane = threadIdx.x & 31;
    int beg = g_rowptr[n], end = g_rowptr[n + 1];

    float4 acc = {0.f, 0.f, 0.f, 0.f};
    for (int j = beg; j < end; j++) {
        int s = g_csr_src[j];
        float4 v = __ldg(&((const float4*)(feat + (size_t)s * 128))[lane]);
        acc.x += v.x; acc.y += v.y; acc.z += v.z; acc.w += v.w;
    }
    int deg = end - beg;
    float inv = (deg > 0) ? 1.f / (float)deg : 0.f;
    float4 o = {acc.x * inv, acc.y * inv, acc.z * inv, acc.w * inv};
    ((float4*)(out + (size_t)n * 128))[lane] = o;
}

// ---------------- weight split: fp32 (K,N) -> bf16 hi/lo, same layout ----------------
__global__ void k_wprep(const float* __restrict__ W, int len,
                        __nv_bfloat16* __restrict__ hi, __nv_bfloat16* __restrict__ lo) {
    int i = blockIdx.x * blockDim.x + threadIdx.x;
    if (i >= len) return;
    float w = W[i];
    __nv_bfloat16 h = __float2bfloat16_rn(w);
    hi[i] = h;
    lo[i] = __float2bfloat16_rn(w - __bfloat162float(h));
}

// ================= bf16x3 mma.sync GEMMs =================
// CTA tile 128(M) x 64(N), BK=32. 8 warps: wm=wid&3 (M), wn=wid>>2 (N).
// Warp tile 32x32 = mma grid 2(M:16) x 4(N:8).
// SMEM: A tiles 128 rows x 40 bf16 (80B row = 16x5, conflict-free ldmatrix);
//       B tiles  32 rows x 72 bf16 (144B row = 16x9, conflict-free ldmatrix).
#define A_TILE_B 10240
#define B_TILE_B 4608

// -------- layer 1: C = relu(A1@B1 + A2@B2 + bias) --------
__global__ void __launch_bounds__(256) k_mm_dual(
    const float* __restrict__ A1, const float* __restrict__ A2,
    const __nv_bfloat16* __restrict__ B1h, const __nv_bfloat16* __restrict__ B1l,
    const __nv_bfloat16* __restrict__ B2h, const __nv_bfloat16* __restrict__ B2l,
    const float* __restrict__ bias, float* __restrict__ C,
    int M, int N, int K)
{
    extern __shared__ char smem[];
    const int OA1H = 0, OA1L = A_TILE_B, OA2H = 2 * A_TILE_B, OA2L = 3 * A_TILE_B;
    const int OB1H = 4 * A_TILE_B, OB1L = OB1H + B_TILE_B;
    const int OB2H = OB1H + 2 * B_TILE_B, OB2L = OB1H + 3 * B_TILE_B;
    uint32_t sb = smem_u32(smem);

    int tid = threadIdx.x, lane = tid & 31, wid = tid >> 5;
    int wm = wid & 3, wn = wid >> 2;
    int bm = blockIdx.y * 128, bn = blockIdx.x * 64;

    float acc[2][4][4];
#pragma unroll
    for (int i = 0; i < 2; i++)
#pragma unroll
        for (int j = 0; j < 4; j++)
#pragma unroll
            for (int q = 0; q < 4; q++) acc[i][j][q] = 0.f;

    for (int k0 = 0; k0 < K; k0 += 32) {
        // stage A (split on the fly)
#pragma unroll
        for (int q = 0; q < 4; q++) {
            int slot = tid + q * 256;
            int row = slot >> 3, k4 = (slot & 7) * 4;
            int gr = bm + row;
            float4 v1 = {0.f, 0.f, 0.f, 0.f}, v2 = {0.f, 0.f, 0.f, 0.f};
            if (gr < M) {
                v1 = *(const float4*)(A1 + (size_t)gr * K + k0 + k4);
                v2 = *(const float4*)(A2 + (size_t)gr * K + k0 + k4);
            }
            uint32_t h[2], l[2];
            int si = row * 20 + (k4 >> 1);
            split4(v1, h, l);
            ((uint32_t*)(smem + OA1H))[si] = h[0];
            ((uint32_t*)(smem + OA1H))[si + 1] = h[1];
            ((uint32_t*)(smem + OA1L))[si] = l[0];
            ((uint32_t*)(smem + OA1L))[si + 1] = l[1];
            split4(v2, h, l);
            ((uint32_t*)(smem + OA2H))[si] = h[0];
            ((uint32_t*)(smem + OA2H))[si + 1] = h[1];
            ((uint32_t*)(smem + OA2L))[si] = l[0];
            ((uint32_t*)(smem + OA2L))[si + 1] = l[1];
        }
        // stage B (pre-split)
#pragma unroll
        for (int q = 0; q < 4; q++) {
            int slot = tid + q * 256;
            int k = slot >> 5, n2 = slot & 31;
            size_t gu = (((size_t)(k0 + k) * N + bn) >> 1) + n2;
            int si = k * 36 + n2;
            ((uint32_t*)(smem + OB1H))[si] = ((const uint32_t*)B1h)[gu];
            ((uint32_t*)(smem + OB1L))[si] = ((const uint32_t*)B1l)[gu];
            ((uint32_t*)(smem + OB2H))[si] = ((const uint32_t*)B2h)[gu];
            ((uint32_t*)(smem + OB2L))[si] = ((const uint32_t*)B2l)[gu];
        }
        __syncthreads();

#pragma unroll
        for (int kk = 0; kk < 2; kk++) {
            uint32_t fa1h[2][4], fa1l[2][4], fa2h[2][4], fa2l[2][4];
#pragma unroll
            for (int mi = 0; mi < 2; mi++) {
                uint32_t aoff = (uint32_t)((wm * 32 + mi * 16 + (lane & 15)) * 80 +
                                           (lane >> 4) * 16 + kk * 32);
                LDSM_X4(fa1h[mi][0], fa1h[mi][1], fa1h[mi][2], fa1h[mi][3], sb + OA1H + aoff);
                LDSM_X4(fa1l[mi][0], fa1l[mi][1], fa1l[mi][2], fa1l[mi][3], sb + OA1L + aoff);
                LDSM_X4(fa2h[mi][0], fa2h[mi][1], fa2h[mi][2], fa2h[mi][3], sb + OA2H + aoff);
                LDSM_X4(fa2l[mi][0], fa2l[mi][1], fa2l[mi][2], fa2l[mi][3], sb + OA2L + aoff);
            }
            uint32_t fb1h[4][2], fb1l[4][2], fb2h[4][2], fb2l[4][2];
#pragma unroll
            for (int np = 0; np < 2; np++) {
                uint32_t boff = (uint32_t)((kk * 16 + (lane & 7) + ((lane >> 3) & 1) * 8) * 144 +
                                           wn * 64 + np * 32 + (lane >> 4) * 16);
                LDSM_X4T(fb1h[2 * np][0], fb1h[2 * np][1], fb1h[2 * np + 1][0], fb1h[2 * np + 1][1], sb + OB1H + boff);
                LDSM_X4T(fb1l[2 * np][0], fb1l[2 * np][1], fb1l[2 * np + 1][0], fb1l[2 * np + 1][1], sb + OB1L + boff);
                LDSM_X4T(fb2h[2 * np][0], fb2h[2 * np][1], fb2h[2 * np + 1][0], fb2h[2 * np + 1][1], sb + OB2H + boff);
                LDSM_X4T(fb2l[2 * np][0], fb2l[2 * np][1], fb2l[2 * np + 1][0], fb2l[2 * np + 1][1], sb + OB2L + boff);
            }
#pragma unroll
            for (int mi = 0; mi < 2; mi++)
#pragma unroll
                for (int nj = 0; nj < 4; nj++) {
                    MMA_BF16(acc[mi][nj], fa1h[mi], fb1h[nj]);
                    MMA_BF16(acc[mi][nj], fa1h[mi], fb1l[nj]);
                    MMA_BF16(acc[mi][nj], fa1l[mi], fb1h[nj]);
                    MMA_BF16(acc[mi][nj], fa2h[mi], fb2h[nj]);
                    MMA_BF16(acc[mi][nj], fa2h[mi], fb2l[nj]);
                    MMA_BF16(acc[mi][nj], fa2l[mi], fb2h[nj]);
                }
        }
        __syncthreads();
    }

    // epilogue
    int g = lane >> 2, c2 = (lane & 3) * 2;
#pragma unroll
    for (int mi = 0; mi < 2; mi++)
#pragma unroll
        for (int nj = 0; nj < 4; nj++) {
            int col = bn + wn * 32 + nj * 8 + c2;
            float2 bv = *(const float2*)(bias + col);
            int r0 = bm + wm * 32 + mi * 16 + g;
            if (r0 < M) {
                float2 o;
                o.x = fmaxf(acc[mi][nj][0] + bv.x, 0.f);
                o.y = fmaxf(acc[mi][nj][1] + bv.y, 0.f);
                *(float2*)(C + (size_t)r0 * N + col) = o;
            }
            int r1 = r0 + 8;
            if (r1 < M) {
                float2 o;
                o.x = fmaxf(acc[mi][nj][2] + bv.x, 0.f);
                o.y = fmaxf(acc[mi][nj][3] + bv.y, 0.f);
                *(float2*)(C + (size_t)r1 * N + col) = o;
            }
        }
}

// -------- layer 2: S = A@Bs + bias, T = A@Bt --------
__global__ void __launch_bounds__(256) k_mm_pair(
    const float* __restrict__ A,
    const __nv_bfloat16* __restrict__ Bsh, const __nv_bfloat16* __restrict__ Bsl,
    const __nv_bfloat16* __restrict__ Bth, const __nv_bfloat16* __restrict__ Btl,
    const float* __restrict__ bias, float* __restrict__ S, float* __restrict__ T,
    int M, int N, int K)
{
    extern __shared__ char smem[];
    const int OAH = 0, OAL = A_TILE_B;
    const int OBSH = 2 * A_TILE_B, OBSL = OBSH + B_TILE_B;
    const int OBTH = OBSH + 2 * B_TILE_B, OBTL = OBSH + 3 * B_TILE_B;
    uint32_t sb = smem_u32(smem);

    int tid = threadIdx.x, lane = tid & 31, wid = tid >> 5;
    int wm = wid & 3, wn = wid >> 2;
    int bm = blockIdx.y * 128, bn = blockIdx.x * 64;

    float accS[2][4][4], accT[2][4][4];
#pragma unroll
    for (int i = 0; i < 2; i++)
#pragma unroll
        for (int j = 0; j < 4; j++)
#pragma unroll
            for (int q = 0; q < 4; q++) { accS[i][j][q] = 0.f; accT[i][j][q] = 0.f; }

    for (int k0 = 0; k0 < K; k0 += 32) {
#pragma unroll
        for (int q = 0; q < 4; q++) {
            int slot = tid + q * 256;
            int row = slot >> 3, k4 = (slot & 7) * 4;
            int gr = bm + row;
            float4 v = {0.f, 0.f, 0.f, 0.f};
            if (gr < M) v = *(const float4*)(A + (size_t)gr * K + k0 + k4);
            uint32_t h[2], l[2];
            split4(v, h, l);
            int si = row * 20 + (k4 >> 1);
            ((uint32_t*)(smem + OAH))[si] = h[0];
            ((uint32_t*)(smem + OAH))[si + 1] = h[1];
            ((uint32_t*)(smem + OAL))[si] = l[0];
            ((uint32_t*)(smem + OAL))[si + 1] = l[1];
        }
#pragma unroll
        for (int q = 0; q < 4; q++) {
            int slot = tid + q * 256;
            int k = slot >> 5, n2 = slot & 31;
            size_t gu = (((size_t)(k0 + k) * N + bn) >> 1) + n2;
            int si = k * 36 + n2;
            ((uint32_t*)(smem + OBSH))[si] = ((const uint32_t*)Bsh)[gu];
            ((uint32_t*)(smem + OBSL))[si] = ((const uint32_t*)Bsl)[gu];
            ((uint32_t*)(smem + OBTH))[si] = ((const uint32_t*)Bth)[gu];
            ((uint32_t*)(smem + OBTL))[si] = ((const uint32_t*)Btl)[gu];
        }
        __syncthreads();

#pragma unroll
        for (int kk = 0; kk < 2; kk++) {
            uint32_t fah[2][4], fal[2][4];
#pragma unroll
            for (int mi = 0; mi < 2; mi++) {
                uint32_t aoff = (uint32_t)((wm * 32 + mi * 16 + (lane & 15)) * 80 +
                                           (lane >> 4) * 16 + kk * 32);
                LDSM_X4(fah[mi][0], fah[mi][1], fah[mi][2], fah[mi][3], sb + OAH + aoff);
                LDSM_X4(fal[mi][0], fal[mi][1], fal[mi][2], fal[mi][3], sb + OAL + aoff);
            }
            uint32_t fbsh[4][2], fbsl[4][2], fbth[4][2], fbtl[4][2];
#pragma unroll
            for (int np = 0; np < 2; np++) {
                uint32_t boff = (uint32_t)((kk * 16 + (lane & 7) + ((lane >> 3) & 1) * 8) * 144 +
                                           wn * 64 + np * 32 + (lane >> 4) * 16);
                LDSM_X4T(fbsh[2 * np][0], fbsh[2 * np][1], fbsh[2 * np + 1][0], fbsh[2 * np + 1][1], sb + OBSH + boff);
                LDSM_X4T(fbsl[2 * np][0], fbsl[2 * np][1], fbsl[2 * np + 1][0], fbsl[2 * np + 1][1], sb + OBSL + boff);
                LDSM_X4T(fbth[2 * np][0], fbth[2 * np][1], fbth[2 * np + 1][0], fbth[2 * np + 1][1], sb + OBTH + boff);
                LDSM_X4T(fbtl[2 * np][0], fbtl[2 * np][1], fbtl[2 * np + 1][0], fbtl[2 * np + 1][1], sb + OBTL + boff);
            }
#pragma unroll
            for (int mi = 0; mi < 2; mi++)
#pragma unroll
                for (int nj = 0; nj < 4; nj++) {
                    MMA_BF16(accS[mi][nj], fah[mi], fbsh[nj]);
                    MMA_BF16(accS[mi][nj], fah[mi], fbsl[nj]);
                    MMA_BF16(accS[mi][nj], fal[mi], fbsh[nj]);
                    MMA_BF16(accT[mi][nj], fah[mi], fbth[nj]);
                    MMA_BF16(accT[mi][nj], fah[mi], fbtl[nj]);
                    MMA_BF16(accT[mi][nj], fal[mi], fbth[nj]);
                }
        }
        __syncthreads();
    }

    int g = lane >> 2, c2 = (lane & 3) * 2;
#pragma unroll
    for (int mi = 0; mi < 2; mi++)
#pragma unroll
        for (int nj = 0; nj < 4; nj++) {
            int col = bn + wn * 32 + nj * 8 + c2;
            float2 bv = *(const float2*)(bias + col);
            int r0 = bm + wm * 32 + mi * 16 + g;
            if (r0 < M) {
                float2 os = {accS[mi][nj][0] + bv.x, accS[mi][nj][1] + bv.y};
                *(float2*)(S + (size_t)r0 * N + col) = os;
                float2 ot = {accT[mi][nj][0], accT[mi][nj][1]};
                *(float2*)(T + (size_t)r0 * N + col) = ot;
            }
            int r1 = r0 + 8;
            if (r1 < M) {
                float2 os = {accS[mi][nj][2] + bv.x, accS[mi][nj][3] + bv.y};
                *(float2*)(S + (size_t)r1 * N + col) = os;
                float2 ot = {accT[mi][nj][2], accT[mi][nj][3]};
                *(float2*)(T + (size_t)r1 * N + col) = ot;
            }
        }
}

// ---------------- fused layer-2 aggregation + node scores ----------------
__global__ void k_agg2_scores(const float* __restrict__ Wp) {
    int warps_per_blk = blockDim.x >> 5;
    int n = blockIdx.x * warps_per_blk + (threadIdx.x >> 5);
    if (n >= N_NODES) return;
    int lane = threadIdx.x & 31;
    int beg = g_rowptr[n], end = g_rowptr[n + 1];

    float4 acc = {0.f, 0.f, 0.f, 0.f};
    for (int j = beg; j < end; j++) {
        int s = g_csr_src[j];
        float4 v = __ldg(&((const float4*)(g_t2 + (size_t)s * 128))[lane]);
        acc.x += v.x; acc.y += v.y; acc.z += v.z; acc.w += v.w;
    }
    int deg = end - beg;
    float inv = (deg > 0) ? 1.f / (float)deg : 0.f;
    float4 sv = ((const float4*)(g_s2 + (size_t)n * 128))[lane];
    float4 h;
    h.x = sv.x + acc.x * inv;
    h.y = sv.y + acc.y * inv;
    h.z = sv.z + acc.z * inv;
    h.w = sv.w + acc.w * inv;

    float4 wa = __ldg(&((const float4*)Wp)[lane]);
    float4 wb = __ldg(&((const float4*)Wp)[lane + 32]);
    float a = h.x * wa.x + h.y * wa.y + h.z * wa.z + h.w * wa.w;
    float b = h.x * wb.x + h.y * wb.y + h.z * wb.z + h.w * wb.w;
#pragma unroll
    for (int off = 16; off; off >>= 1) {
        a += __shfl_down_sync(0xFFFFFFFFu, a, off);
        b += __shfl_down_sync(0xFFFFFFFFu, b, off);
    }
    if (lane == 0) { g_sA[n] = a; g_sB[n] = b; }
}

__global__ void k_edge_scores(const int* __restrict__ psrc, const int* __restrict__ pdst,
                              const int* __restrict__ nsrc, const int* __restrict__ ndst,
                              const float* __restrict__ bp, float* __restrict__ out,
                              int EP, int EN) {
    int i = blockIdx.x * blockDim.x + threadIdx.x;
    float b = bp[0];
    if (i < EP) {
        out[i] = g_sA[psrc[i]] + g_sB[pdst[i]] + b;
    } else if (i < EP + EN) {
        int j = i - EP;
        out[i] = g_sA[nsrc[j]] + g_sB[ndst[j]] + b;
    }
}

// ---------------- launch ----------------
extern "C" void kernel_launch(void* const* d_in, const int* in_sizes, int n_in,
                              void* d_out, int out_size) {
    const float* x    = (const float*)d_in[0];
    const int* msrc   = (const int*)d_in[1];
    const int* mdst   = (const int*)d_in[2];
    const int* psrc   = (const int*)d_in[3];
    const int* pdst   = (const int*)d_in[4];
    const int* nsrc   = (const int*)d_in[5];
    const int* ndst   = (const int*)d_in[6];
    const float* W1s  = (const float*)d_in[7];
    const float* W1n  = (const float*)d_in[8];
    const float* b1   = (const float*)d_in[9];
    const float* W2s  = (const float*)d_in[10];
    const float* W2n  = (const float*)d_in[11];
    const float* b2   = (const float*)d_in[12];
    const float* Wp   = (const float*)d_in[13];
    const float* bp   = (const float*)d_in[14];
    float* out = (float*)d_out;

    int E  = in_sizes[1];
    int EP = in_sizes[3];
    int EN = in_sizes[5];

    float *p_neigh1, *p_h1, *p_s2, *p_t2;
    cudaGetSymbolAddress((void**)&p_neigh1, g_neigh1);
    cudaGetSymbolAddress((void**)&p_h1,     g_h1);
    cudaGetSymbolAddress((void**)&p_s2,     g_s2);
    cudaGetSymbolAddress((void**)&p_t2,     g_t2);

    __nv_bfloat16 *w1sh, *w1sl, *w1nh, *w1nl, *w2sh, *w2sl, *w2nh, *w2nl;
    cudaGetSymbolAddress((void**)&w1sh, g_w1s_h);
    cudaGetSymbolAddress((void**)&w1sl, g_w1s_l);
    cudaGetSymbolAddress((void**)&w1nh, g_w1n_h);
    cudaGetSymbolAddress((void**)&w1nl, g_w1n_l);
    cudaGetSymbolAddress((void**)&w2sh, g_w2s_h);
    cudaGetSymbolAddress((void**)&w2sl, g_w2s_l);
    cudaGetSymbolAddress((void**)&w2nh, g_w2n_h);
    cudaGetSymbolAddress((void**)&w2nl, g_w2n_l);

    const int SMEM_DUAL = 4 * A_TILE_B + 4 * B_TILE_B;  // 59392
    const int SMEM_PAIR = 2 * A_TILE_B + 4 * B_TILE_B;  // 38912
    cudaFuncSetAttribute(k_mm_dual, cudaFuncAttributeMaxDynamicSharedMemorySize, SMEM_DUAL);
    cudaFuncSetAttribute(k_mm_pair, cudaFuncAttributeMaxDynamicSharedMemorySize, SMEM_PAIR);

    // CSR build
    k_zero_cnt<<<(N_NODES + 255) / 256, 256>>>();
    k_hist<<<(E + 255) / 256, 256>>>(mdst, E);
    k_scan<<<1, 1024>>>();
    k_fill<<<(E + 255) / 256, 256>>>(msrc, mdst, E);

    // weight split
    k_wprep<<<(D_IN * D_HID + 255) / 256, 256>>>(W1s, D_IN * D_HID, w1sh, w1sl);
    k_wprep<<<(D_IN * D_HID + 255) / 256, 256>>>(W1n, D_IN * D_HID, w1nh, w1nl);
    k_wprep<<<(D_HID * D_OUT + 255) / 256, 256>>>(W2s, D_HID * D_OUT, w2sh, w2sl);
    k_wprep<<<(D_HID * D_OUT + 255) / 256, 256>>>(W2n, D_HID * D_OUT, w2nh, w2nl);

    // layer 1
    k_agg128<<<(N_NODES + 7) / 8, 256>>>(x, p_neigh1);
    {
        dim3 grid(D_HID / 64, (N_NODES + 127) / 128);
        k_mm_dual<<<grid, 256, SMEM_DUAL>>>(x, p_neigh1, w1sh, w1sl, w1nh, w1nl,
                                            b1, p_h1, N_NODES, D_HID, D_IN);
    }
    // layer 2: project then aggregate
    {
        dim3 grid(D_OUT / 64, (N_NODES + 127) / 128);
        k_mm_pair<<<grid, 256, SMEM_PAIR>>>(p_h1, w2sh, w2sl, w2nh, w2nl,
                                            b2, p_s2, p_t2, N_NODES, D_OUT, D_HID);
    }
    k_agg2_scores<<<(N_NODES + 7) / 8, 256>>>(Wp);

    // edge scoring
    k_edge_scores<<<(EP + EN + 255) / 256, 256>>>(psrc, pdst, nsrc, ndst, bp, out, EP, EN);
}